// round 17
// baseline (speedup 1.0000x reference)
#include <cuda_runtime.h>
#include <cuda_fp16.h>
#include <cstdint>
#include <math_constants.h>

#define T_DIM 64
#define B_DIM 32
#define S_DIM 128
#define E_DIM 512
#define Q_DIM 512
#define H_DIM 256

#define HSTR 40   // halves per smem row (32 data + 8 pad) -> conflict-free frags

// Scratch (device globals — no allocation allowed)
__device__ __half g_src_proj_h[B_DIM * H_DIM * S_DIM];  // [b][h][s], f16
__device__ __half g_q_proj_h[T_DIM * B_DIM * H_DIM];    // [t][b][h], f16 (same rounding point)

__device__ __forceinline__ float ex2f_(float x) {
    float y; asm("ex2.approx.f32 %0, %1;" : "=f"(y) : "f"(x)); return y;
}
__device__ __forceinline__ unsigned h2tanh_(unsigned x) {
    unsigned y; asm("tanh.approx.f16x2 %0, %1;" : "=r"(y) : "r"(x)); return y;
}
__device__ __forceinline__ void mma_f16(float c[4], const unsigned a[4], const unsigned b[2]) {
    asm volatile(
        "mma.sync.aligned.m16n8k16.row.col.f32.f16.f16.f32 "
        "{%0,%1,%2,%3}, {%4,%5,%6,%7}, {%8,%9}, {%0,%1,%2,%3};"
        : "+f"(c[0]), "+f"(c[1]), "+f"(c[2]), "+f"(c[3])
        : "r"(a[0]), "r"(a[1]), "r"(a[2]), "r"(a[3]), "r"(b[0]), "r"(b[1]));
}

// ---------------------------------------------------------------------------
// FP16 tensor-core projection GEMM. Mainloop unchanged (measured ~14 us).
// Both epilogues now emit __half (RNE after f32 bias add — numerically
// identical rounding point to the previous f32-store + downstream convert).
// ---------------------------------------------------------------------------
__global__ __launch_bounds__(512) void proj_gemm(
    const float* __restrict__ src, const float* __restrict__ Wsrc, const float* __restrict__ bsrc,
    const float* __restrict__ qv,  const float* __restrict__ Wq,   const float* __restrict__ bq)
{
    __shared__ __align__(16) __half As[2][128][HSTR];
    __shared__ __align__(16) __half Bs[2][64][HSTR];

    const int bx = blockIdx.x;      // 0..47
    const int n0 = blockIdx.y * 64; // h tile base

    const bool is_src = (bx < 32);
    const float* __restrict__ A    = is_src ? (src + (size_t)bx * 128 * E_DIM)
                                            : (qv  + (size_t)(bx - 32) * 128 * Q_DIM);
    const float* __restrict__ W    = is_src ? Wsrc : Wq;
    const float* __restrict__ bias = is_src ? bsrc : bq;

    const int tid  = threadIdx.x;
    const int warp = tid >> 5;
    const int lane = tid & 31;
    const int wm   = (warp & 3) * 32;
    const int wn   = (warp >> 2) * 16;
    const int frow = lane >> 2;
    const int fcol = lane & 3;

    float acc[2][2][4];
#pragma unroll
    for (int i = 0; i < 2; i++)
#pragma unroll
        for (int j = 0; j < 2; j++)
#pragma unroll
            for (int r = 0; r < 4; r++) acc[i][j][r] = 0.f;

    float4 ra0, ra1, rb;
    const int a_r0 = tid >> 3;
    const int a_r1 = (tid + 512) >> 3;
    const int a_c  = (tid & 7) * 4;

    auto ldg_chunk = [&](int kc) {
        const int kt = kc * 32;
        ra0 = *(const float4*)&A[(size_t)a_r0 * 512 + kt + a_c];
        ra1 = *(const float4*)&A[(size_t)a_r1 * 512 + kt + a_c];
        rb  = *(const float4*)&W[(size_t)(n0 + a_r0) * 512 + kt + a_c];
    };
    auto sts_chunk = [&](int buf) {
        *(__half2*)&As[buf][a_r0][a_c    ] = __floats2half2_rn(ra0.x, ra0.y);
        *(__half2*)&As[buf][a_r0][a_c + 2] = __floats2half2_rn(ra0.z, ra0.w);
        *(__half2*)&As[buf][a_r1][a_c    ] = __floats2half2_rn(ra1.x, ra1.y);
        *(__half2*)&As[buf][a_r1][a_c + 2] = __floats2half2_rn(ra1.z, ra1.w);
        *(__half2*)&Bs[buf][a_r0][a_c    ] = __floats2half2_rn(rb.x, rb.y);
        *(__half2*)&Bs[buf][a_r0][a_c + 2] = __floats2half2_rn(rb.z, rb.w);
    };

    ldg_chunk(0);
    sts_chunk(0);

    for (int kc = 0; kc < 16; kc++) {
        __syncthreads();
        if (kc + 1 < 16) ldg_chunk(kc + 1);

        const int buf = kc & 1;
#pragma unroll
        for (int ks = 0; ks < 2; ks++) {
            const int kb = ks * 16 + fcol * 2;
            unsigned ah[2][4];
#pragma unroll
            for (int mf = 0; mf < 2; mf++) {
                const int m = wm + mf * 16 + frow;
                ah[mf][0] = *(const unsigned*)&As[buf][m    ][kb    ];
                ah[mf][1] = *(const unsigned*)&As[buf][m + 8][kb    ];
                ah[mf][2] = *(const unsigned*)&As[buf][m    ][kb + 8];
                ah[mf][3] = *(const unsigned*)&As[buf][m + 8][kb + 8];
            }
            unsigned bh[2][2];
#pragma unroll
            for (int nf = 0; nf < 2; nf++) {
                const int n = wn + nf * 8 + frow;
                bh[nf][0] = *(const unsigned*)&Bs[buf][n][kb    ];
                bh[nf][1] = *(const unsigned*)&Bs[buf][n][kb + 8];
            }
#pragma unroll
            for (int mf = 0; mf < 2; mf++)
#pragma unroll
                for (int nf = 0; nf < 2; nf++)
                    mma_f16(acc[mf][nf], ah[mf], bh[nf]);
        }

        if (kc + 1 < 16) sts_chunk((kc + 1) & 1);
    }

    const int crow = lane >> 2;
    const int ccol = (lane & 3) * 2;

    if (is_src) {
        const int b = bx;
        __half* dst = g_src_proj_h + (size_t)b * H_DIM * S_DIM;
#pragma unroll
        for (int mf = 0; mf < 2; mf++)
#pragma unroll
            for (int nf = 0; nf < 2; nf++) {
                const int s0  = wm + mf * 16 + crow;
                const int h0g = n0 + wn + nf * 8 + ccol;
                dst[(h0g    ) * S_DIM + s0    ] = __float2half_rn(acc[mf][nf][0] + bias[h0g    ]);
                dst[(h0g + 1) * S_DIM + s0    ] = __float2half_rn(acc[mf][nf][1] + bias[h0g + 1]);
                dst[(h0g    ) * S_DIM + s0 + 8] = __float2half_rn(acc[mf][nf][2] + bias[h0g    ]);
                dst[(h0g + 1) * S_DIM + s0 + 8] = __float2half_rn(acc[mf][nf][3] + bias[h0g + 1]);
            }
    } else {
        const int m0 = (bx - 32) * 128;
#pragma unroll
        for (int mf = 0; mf < 2; mf++)
#pragma unroll
            for (int nf = 0; nf < 2; nf++) {
                const int m   = m0 + wm + mf * 16 + crow;
                const int h0g = n0 + wn + nf * 8 + ccol;
                g_q_proj_h[(size_t)m * H_DIM + h0g    ]       = __float2half_rn(acc[mf][nf][0] + bias[h0g    ]);
                g_q_proj_h[(size_t)m * H_DIM + h0g + 1]       = __float2half_rn(acc[mf][nf][1] + bias[h0g + 1]);
                g_q_proj_h[(size_t)(m + 8) * H_DIM + h0g    ] = __float2half_rn(acc[mf][nf][2] + bias[h0g    ]);
                g_q_proj_h[(size_t)(m + 8) * H_DIM + h0g + 1] = __float2half_rn(acc[mf][nf][3] + bias[h0g + 1]);
            }
    }
}

// ---------------------------------------------------------------------------
// Fused kernel v4 — all-f16 loop, f16 scratch both sides, minBlocks=4 to
// force regs<=32 and raise occupancy to 4 CTA/SM (xu duty 63% -> ~85%+).
// ---------------------------------------------------------------------------
__global__ __launch_bounds__(512, 4) void fused_attn(
    const float* __restrict__ w2, const float* __restrict__ b2p,
    const int* __restrict__ mask, float* __restrict__ out)
{
    const int b   = blockIdx.y;
    const int tg  = blockIdx.x;            // t = tg*4 + tt
    const int tid = threadIdx.x;

    __shared__ unsigned w2h[H_DIM];        // half2(w,w)
    __shared__ uint4    qpk[H_DIM];        // {half2(q0,q0),...,half2(q3,q3)}
    __shared__ float    part[4][8][S_DIM]; // 16 KB
    __shared__ float    redm[4][4];
    __shared__ float    reds[4][4];

    const float LOG2E = 1.442695040888963407f;

    for (int idx = tid; idx < 4 * H_DIM; idx += 512) {
        const int tt = idx >> 8;
        const int h  = idx & (H_DIM - 1);
        const int t  = tg * 4 + tt;
        const __half hq = g_q_proj_h[((size_t)t * B_DIM + b) * H_DIM + h];
        const __half2 d = __half2half2(hq);
        ((unsigned*)&qpk[h])[tt] = *(const unsigned*)&d;
    }
    if (tid < H_DIM) {
        const __half hw = __float2half_rn(w2[tid]);
        const __half2 d = __half2half2(hw);
        w2h[tid] = *(const unsigned*)&d;
    }
    __syncthreads();

    const int sp  = tid & 63;
    const int hgr = tid >> 6;              // 0..7
    const int s0  = sp * 2;
    const int h0  = hgr * 32;

    const __half* __restrict__ srcp = g_src_proj_h + (size_t)b * H_DIM * S_DIM + s0;

    float facc[4][2];
#pragma unroll
    for (int t = 0; t < 4; t++) { facc[t][0] = 0.f; facc[t][1] = 0.f; }

#pragma unroll
    for (int c = 0; c < 4; c++) {
        __half2 hacc0 = __floats2half2_rn(0.f, 0.f);
        __half2 hacc1 = hacc0, hacc2 = hacc0, hacc3 = hacc0;

#pragma unroll
        for (int i = 0; i < 8; i++) {
            const int h = h0 + c * 8 + i;
            const __half2 sv2 = *(const __half2*)&srcp[(size_t)h * S_DIM];
            const uint4 qp = qpk[h];
            const unsigned wv = w2h[h];
            const __half2 wh = *(const __half2*)&wv;

            __half2 a0 = __hadd2(sv2, *(const __half2*)&qp.x);
            __half2 a1 = __hadd2(sv2, *(const __half2*)&qp.y);
            __half2 a2 = __hadd2(sv2, *(const __half2*)&qp.z);
            __half2 a3 = __hadd2(sv2, *(const __half2*)&qp.w);
            unsigned t0 = h2tanh_(*(const unsigned*)&a0);
            unsigned t1 = h2tanh_(*(const unsigned*)&a1);
            unsigned t2 = h2tanh_(*(const unsigned*)&a2);
            unsigned t3 = h2tanh_(*(const unsigned*)&a3);
            hacc0 = __hfma2(wh, *(const __half2*)&t0, hacc0);
            hacc1 = __hfma2(wh, *(const __half2*)&t1, hacc1);
            hacc2 = __hfma2(wh, *(const __half2*)&t2, hacc2);
            hacc3 = __hfma2(wh, *(const __half2*)&t3, hacc3);
        }
        {
            const float2 f0 = __half22float2(hacc0);
            const float2 f1 = __half22float2(hacc1);
            const float2 f2 = __half22float2(hacc2);
            const float2 f3 = __half22float2(hacc3);
            facc[0][0] += f0.x; facc[0][1] += f0.y;
            facc[1][0] += f1.x; facc[1][1] += f1.y;
            facc[2][0] += f2.x; facc[2][1] += f2.y;
            facc[3][0] += f3.x; facc[3][1] += f3.y;
        }
    }

#pragma unroll
    for (int t = 0; t < 4; t++)
        *(float2*)&part[t][hgr][s0] = make_float2(facc[t][0], facc[t][1]);
    __syncthreads();

    const int s    = tid & 127;
    const int ttg  = tid >> 7;
    const int lane = tid & 31;
    const int gw   = (tid >> 5) & 3;

    float logit = b2p[0];
#pragma unroll
    for (int g = 0; g < 8; g++)
        logit += part[ttg][g][s];
    if (mask[b * S_DIM + s] != 0)
        logit = __int_as_float(0xff800000);

    float m = logit;
#pragma unroll
    for (int off = 16; off >= 1; off >>= 1)
        m = fmaxf(m, __shfl_xor_sync(0xffffffffu, m, off));
    if (lane == 0) redm[ttg][gw] = m;
    __syncthreads();

    const float bm = fmaxf(fmaxf(redm[ttg][0], redm[ttg][1]),
                           fmaxf(redm[ttg][2], redm[ttg][3]));
    const float e = ex2f_((logit - bm) * LOG2E);
    float sum = e;
#pragma unroll
    for (int off = 16; off >= 1; off >>= 1)
        sum += __shfl_xor_sync(0xffffffffu, sum, off);
    if (lane == 0) reds[ttg][gw] = sum;
    __syncthreads();

    const float tot = (reds[ttg][0] + reds[ttg][1]) + (reds[ttg][2] + reds[ttg][3]);
    const int t = tg * 4 + ttg;
    out[((size_t)t * B_DIM + b) * S_DIM + s] = e / tot;
}

extern "C" void kernel_launch(void* const* d_in, const int* in_sizes, int n_in,
                              void* d_out, int out_size)
{
    const float* src  = (const float*)d_in[0];
    const int*   mask = (const int*)d_in[1];
    const float* qv   = (const float*)d_in[2];
    const float* Wsrc = (const float*)d_in[3];
    const float* bsrc = (const float*)d_in[4];
    const float* Wq   = (const float*)d_in[5];
    const float* bq   = (const float*)d_in[6];
    const float* w2   = (const float*)d_in[7];
    const float* b2   = (const float*)d_in[8];
    float*       out  = (float*)d_out;

    dim3 g1(48, 4);
    proj_gemm<<<g1, 512>>>(src, Wsrc, bsrc, qv, Wq, bq);

    dim3 g2(T_DIM / 4, B_DIM);
    fused_attn<<<g2, 512>>>(w2, b2, mask, out);
}